// round 7
// baseline (speedup 1.0000x reference)
#include <cuda_runtime.h>
#include <cuda_bf16.h>

// Problem constants (HungarianMatcher: B=16, Q=900, C=92, T=1600)
#define BQ   14400      // B*Q
#define NC   92         // num classes
#define NT   1600       // num targets

#define QT   45         // queries per block tile (14400 = 320*45)
#define THREADS 160     // threads per block; each owns 2 targets -> 320 t/block

// Scratch: softmax probabilities [BQ, NC]  (5.3 MB, static device array — no allocs)
__device__ float g_prob[BQ * NC];

// ---------------------------------------------------------------------------
// Kernel 1: row-wise softmax of pred_logits [BQ, NC] -> g_prob.
// Warp per row; 92 floats = 23 float4, lanes 0..22 own one float4 each.
// Row base = row*368 bytes, 16B-aligned -> float4 loads/stores are legal.
// ---------------------------------------------------------------------------
__global__ void softmax_rows_kernel(const float* __restrict__ logits) {
    int row = blockIdx.x * (blockDim.x >> 5) + (threadIdx.x >> 5);
    if (row >= BQ) return;
    int lane = threadIdx.x & 31;
    bool act = lane < 23;

    const float4* in = reinterpret_cast<const float4*>(logits + (size_t)row * NC);
    float4 v = act ? in[lane] : make_float4(-1e30f, -1e30f, -1e30f, -1e30f);

    float m = fmaxf(fmaxf(v.x, v.y), fmaxf(v.z, v.w));
    #pragma unroll
    for (int o = 16; o; o >>= 1) m = fmaxf(m, __shfl_xor_sync(0xffffffffu, m, o));

    // exp(-1e30 - m) underflows to 0 -> inactive lanes contribute nothing.
    float4 e = make_float4(__expf(v.x - m), __expf(v.y - m),
                           __expf(v.z - m), __expf(v.w - m));

    float s = (e.x + e.y) + (e.z + e.w);
    #pragma unroll
    for (int o = 16; o; o >>= 1) s += __shfl_xor_sync(0xffffffffu, s, o);

    float r = __fdividef(1.0f, s);
    if (act) {
        float4* outp = reinterpret_cast<float4*>(g_prob + (size_t)row * NC);
        outp[lane] = make_float4(e.x * r, e.y * r, e.z * r, e.w * r);
    }
}

// ---------------------------------------------------------------------------
// Per-pair cost (~31 SASS ops). Enclosing-box identity:
//   ew = (wp + wt) - iwu   (max(a,b)+min(a,b) = a+b)
// ---------------------------------------------------------------------------
__device__ __forceinline__ float pair_cost(
        float4 pc, float4 pxy, float area_p,
        float tx0, float ty0, float tx1, float ty1,
        float tcx, float tcy, float tw, float th,
        float area_t, float nprob) {
    float ax  = fmaxf(pxy.x, tx0);
    float bx  = fminf(pxy.z, tx1);
    float iwu = bx - ax;                       // unclamped intersection w
    float ay  = fmaxf(pxy.y, ty0);
    float by  = fminf(pxy.w, ty1);
    float ihu = by - ay;

    float iw = fmaxf(iwu, 0.0f);
    float ih = fmaxf(ihu, 0.0f);
    float inter = iw * ih;

    float ew  = (pc.z + tw) - iwu;             // enclosing w via identity
    float eh  = (pc.w + th) - ihu;
    float enc = ew * eh;

    float uni = (area_p + area_t) - inter;
    float emu = enc - uni;
    float num = fmaf(inter, enc, -emu * uni);  // inter*enc - (enc-uni)*uni
    float giou = __fdividef(num, uni * enc);

    float cb = fabsf(pc.x - tcx) + fabsf(pc.y - tcy)
             + fabsf(pc.z - tw)  + fabsf(pc.w - th);

    return fmaf(5.0f, cb, fmaf(-2.0f, giou, nprob));
}

// ---------------------------------------------------------------------------
// Kernel 2: pair cost, q-tiled, dual-target threads.
// grid = (NT/(2*THREADS) = 5, BQ/QT = 320), block = 160.
// launch_bounds(160,10): force regs<=40 so 10 blocks/SM are resident
// (1600 blocks -> 1.08 waves instead of 1.35).
// ---------------------------------------------------------------------------
__global__ __launch_bounds__(THREADS, 10) void cost_kernel(
        const float* __restrict__ pred_boxes,   // [BQ,4] cxcywh
        const int*   __restrict__ tgt_labels,   // [NT] int32
        const float* __restrict__ tgt_boxes,    // [NT,4] cxcywh
        float*       __restrict__ out) {
    __shared__ float4 s_xy[QT];            // pred xyxy
    __shared__ float4 s_cw[QT];            // pred cxcywh
    __shared__ float  s_prob[QT * NC];     // softmax rows for this q-tile

    const int tid = threadIdx.x;
    const int q0  = blockIdx.y * QT;

    // float4 fill of the probability tile: 45*92 = 4140 floats = 1035 float4.
    // Tile base offset q0*NC*4 = blockIdx.y*16560 bytes -> 16B aligned.
    {
        const float4* gp4 = reinterpret_cast<const float4*>(g_prob + (size_t)q0 * NC);
        float4* sp4 = reinterpret_cast<float4*>(s_prob);
        #pragma unroll
        for (int i = tid; i < (QT * NC) / 4; i += THREADS) sp4[i] = gp4[i];
    }

    if (tid < QT) {
        float4 b = reinterpret_cast<const float4*>(pred_boxes)[q0 + tid];
        s_cw[tid] = b;
        s_xy[tid] = make_float4(b.x - 0.5f * b.z, b.y - 0.5f * b.w,
                                b.x + 0.5f * b.z, b.y + 0.5f * b.w);
    }
    __syncthreads();

    // Two adjacent targets per thread, loaded once.
    const int t0 = blockIdx.x * (2 * THREADS) + 2 * tid;
    float4 ta = reinterpret_cast<const float4*>(tgt_boxes)[t0];
    float4 tb = reinterpret_cast<const float4*>(tgt_boxes)[t0 + 1];
    int la = min(max(tgt_labels[t0],     0), NC - 1);
    int lb = min(max(tgt_labels[t0 + 1], 0), NC - 1);

    const float ax0 = ta.x - 0.5f * ta.z, ay0 = ta.y - 0.5f * ta.w;
    const float ax1 = ta.x + 0.5f * ta.z, ay1 = ta.y + 0.5f * ta.w;
    const float areaA = ta.z * ta.w;

    const float bx0 = tb.x - 0.5f * tb.z, by0 = tb.y - 0.5f * tb.w;
    const float bx1 = tb.x + 0.5f * tb.z, by1 = tb.y + 0.5f * tb.w;
    const float areaB = tb.z * tb.w;

    float2* outp = reinterpret_cast<float2*>(out + (size_t)q0 * NT + t0);

    #pragma unroll 9
    for (int j = 0; j < QT; j++) {
        float4 pxy = s_xy[j];              // warp-uniform LDS.128 broadcast
        float4 pc  = s_cw[j];
        float  area_p = pc.z * pc.w;       // shared by both pairs
        const float* pr = s_prob + j * NC;

        float c0 = pair_cost(pc, pxy, area_p, ax0, ay0, ax1, ay1,
                             ta.x, ta.y, ta.z, ta.w, areaA, -pr[la]);
        float c1 = pair_cost(pc, pxy, area_p, bx0, by0, bx1, by1,
                             tb.x, tb.y, tb.z, tb.w, areaB, -pr[lb]);

        outp[(size_t)j * (NT / 2)] = make_float2(c0, c1);
    }
}

// ---------------------------------------------------------------------------
extern "C" void kernel_launch(void* const* d_in, const int* in_sizes, int n_in,
                              void* d_out, int out_size) {
    const float* pred_logits = (const float*)d_in[0];  // [16,900,92]
    const float* pred_boxes  = (const float*)d_in[1];  // [16,900,4]
    const int*   tgt_labels  = (const int*)  d_in[2];  // [1600] int32
    const float* tgt_boxes   = (const float*)d_in[3];  // [1600,4]
    float*       out         = (float*)d_out;          // [16,900,1600]

    (void)in_sizes; (void)n_in; (void)out_size;

    // Kernel 1: softmax rows. 8 warps/block -> 1800 blocks.
    {
        int warps_per_block = 8;
        int threads = warps_per_block * 32;
        int blocks  = (BQ + warps_per_block - 1) / warps_per_block;
        softmax_rows_kernel<<<blocks, threads>>>(pred_logits);
    }

    // Kernel 2: pair costs. grid (5, 320), 160 threads, 2 targets/thread.
    {
        dim3 block(THREADS, 1, 1);
        dim3 grid(NT / (2 * THREADS), BQ / QT, 1);
        cost_kernel<<<grid, block>>>(pred_boxes, tgt_labels, tgt_boxes, out);
    }
}